// round 13
// baseline (speedup 1.0000x reference)
#include <cuda_runtime.h>
#include <stdint.h>

typedef unsigned long long ULL;

// ---------------- problem constants ----------------
#define C_IN   8
#define HW     256
#define M_OUT  8
#define P_OUT  254
#define PLANE  (P_OUT * P_OUT)

// ---------------- batch split: MMA blocks take n<NA, FFMA2 blocks the rest ----
#define NA        46
#define MMA_BLKS  (NA * 32)            // 1472 (32 y-blocks per n)
#define FMA_BLKS  ((64 - NA) * 64)     // 1152 (8x8 tiles of 32x32 per n)
// interleave: every 41 blocks = 23 MMA + 18 FFMA2 ; 64 groups total
#define GRP_MMA   23
#define GRP_SZ    41
#define TOTAL_BLKS (MMA_BLKS + FMA_BLKS)   // 2624 = 64*41

// ---------------- MMA-path tiling (R9) ----------------
#define YB        8
#define ROWS_ST   (YB + 2)
#define CH_STRIDE 264                       // mod 32 == 8 -> conflict-free
#define ROW_STRIDE (C_IN * CH_STRIDE)       // 2112
#define SMEM_BYTES (ROWS_ST * ROW_STRIDE * 4)   // 84480

// ---------------- FFMA2-path tiling (R4 widened to 256 thr, 32x32 tile) ----------------
#define F_TILE    32
#define F_IN_W    36
#define F_IN_H    34
#define F_CSTR    (F_IN_H * F_IN_W)         // 1224 floats
#define F_WS_ULL  584                       // m*73 + c*9 + r*3 + s
#define F_SIN_OFF 4672                      // bytes; 584*8

__device__ __forceinline__ uint32_t f2tf32(float f) {
    uint32_t r;
    asm("cvt.rna.tf32.f32 %0, %1;" : "=r"(r) : "f"(f));
    return r;
}
__device__ __forceinline__ ULL fma2(ULL a, ULL b, ULL c) {
    ULL d;
    asm("fma.rn.f32x2 %0, %1, %2, %3;" : "=l"(d) : "l"(a), "l"(b), "l"(c));
    return d;
}
__device__ __forceinline__ ULL pack2(unsigned lo, unsigned hi) {
    ULL r;
    asm("mov.b64 %0, {%1, %2};" : "=l"(r) : "r"(lo), "r"(hi));
    return r;
}
__device__ __forceinline__ void unpack2(ULL v, unsigned &lo, unsigned &hi) {
    asm("mov.b64 {%0, %1}, %2;" : "=r"(lo), "=r"(hi) : "l"(v));
}
__device__ __forceinline__ void load_row(uint32_t* A, const uint32_t* p, int tig) {
    #pragma unroll
    for (int ch2 = 0; ch2 < 2; ch2++) {
        const uint32_t* q = p + (tig + ch2 * 4) * CH_STRIDE;
        A[ch2 * 6 + 0] = q[0];
        A[ch2 * 6 + 1] = q[1];
        A[ch2 * 6 + 2] = q[2];
        A[ch2 * 6 + 3] = q[8];
        A[ch2 * 6 + 4] = q[9];
        A[ch2 * 6 + 5] = q[10];
    }
}

__global__ __launch_bounds__(256, 2)
void conv_hybrid_kernel(const float* __restrict__ in,
                        const float* __restrict__ flt,
                        float* __restrict__ out) {
    extern __shared__ char smem_raw[];
    const int tid  = threadIdx.x;
    const int grp  = blockIdx.x / GRP_SZ;
    const int rr   = blockIdx.x % GRP_SZ;

    if (rr < GRP_MMA) {
        // ================= MMA path (tensor pipe), n in [0, NA) =================
        uint32_t* sin_ = (uint32_t*)smem_raw;   // tf32 bits [row0..9][c][px s264]
        const int job  = grp * GRP_MMA + rr;    // 0..1471
        const int n    = job >> 5;
        const int y0   = (job & 31) * YB;
        const int w    = tid >> 5;
        const int lane = tid & 31;
        const int gid  = lane >> 2;
        const int tig  = lane & 3;

        const float* inb = in + (size_t)n * (C_IN * HW * HW);

        #pragma unroll
        for (int it = 0; it < 20; it++) {
            int i   = tid + it * 256;
            int row = i >> 9;
            int c   = (i >> 6) & 7;
            int x4  = i & 63;
            int gy  = y0 + row;
            float4 v = make_float4(0.f, 0.f, 0.f, 0.f);
            if (gy < HW) v = *(const float4*)(inb + (c * HW + gy) * HW + x4 * 4);
            uint4 t = make_uint4(f2tf32(v.x), f2tf32(v.y), f2tf32(v.z), f2tf32(v.w));
            *(uint4*)(sin_ + row * ROW_STRIDE + c * CH_STRIDE + x4 * 4) = t;
        }
        for (int i = tid; i < ROWS_ST * C_IN * 8; i += 256) {
            int row = i >> 6;
            int c   = (i >> 3) & 7;
            sin_[row * ROW_STRIDE + c * CH_STRIDE + 256 + (i & 7)] = 0u;
        }

        uint32_t b0[9], b1[9];
        #pragma unroll
        for (int rs = 0; rs < 9; rs++) {
            int r = rs / 3, s = rs % 3;
            b0[rs] = f2tf32(flt[((gid * 8 + tig) * 3 + r) * 3 + s]);
            b1[rs] = f2tf32(flt[((gid * 8 + tig + 4) * 3 + r) * 3 + s]);
        }
        __syncthreads();

        #pragma unroll 1
        for (int col = 0; col < 2; col++) {
            const int xb = (w + col * 8) * 16;
            const int g  = xb + gid;
            const uint32_t* base = sin_ + g;

            uint32_t A[3][12];
            load_row(A[0], base + 0 * ROW_STRIDE, tig);
            load_row(A[1], base + 1 * ROW_STRIDE, tig);

            #pragma unroll
            for (int yi = 0; yi < YB; yi++) {
                load_row(A[(yi + 2) % 3], base + (yi + 2) * ROW_STRIDE, tig);

                float acc[3][4];
                #pragma unroll
                for (int r = 0; r < 3; r++)
                    acc[r][0] = acc[r][1] = acc[r][2] = acc[r][3] = 0.f;

                #pragma unroll
                for (int s = 0; s < 3; s++) {
                    #pragma unroll
                    for (int r = 0; r < 3; r++) {
                        const uint32_t* Ar = A[(yi + r) % 3];
                        const int rs = r * 3 + s;
                        asm volatile(
                            "mma.sync.aligned.m16n8k8.row.col.f32.tf32.tf32.f32 "
                            "{%0,%1,%2,%3}, {%4,%5,%6,%7}, {%8,%9}, {%0,%1,%2,%3};"
                            : "+f"(acc[r][0]), "+f"(acc[r][1]), "+f"(acc[r][2]), "+f"(acc[r][3])
                            : "r"(Ar[s]), "r"(Ar[3 + s]), "r"(Ar[6 + s]), "r"(Ar[9 + s]),
                              "r"(b0[rs]), "r"(b1[rs]));
                    }
                }

                const int y = y0 + yi;
                if (y < P_OUT) {
                    float c0 = acc[0][0] + acc[1][0] + acc[2][0];
                    float c1 = acc[0][1] + acc[1][1] + acc[2][1];
                    float c2 = acc[0][2] + acc[1][2] + acc[2][2];
                    float c3 = acc[0][3] + acc[1][3] + acc[2][3];
                    float* ob = out + (size_t)(n * M_OUT) * PLANE + (size_t)y * P_OUT;
                    ob[(2 * tig    ) * PLANE + g] = c0;
                    ob[(2 * tig + 1) * PLANE + g] = c1;
                    if (g + 8 < P_OUT) {
                        ob[(2 * tig    ) * PLANE + g + 8] = c2;
                        ob[(2 * tig + 1) * PLANE + g + 8] = c3;
                    }
                }
            }
        }
    } else {
        // ================= FFMA2 path (fma pipe), n in [NA, 64) =================
        ULL*   ws   = (ULL*)smem_raw;                       // 584 splatted weights
        float* sinf = (float*)(smem_raw + F_SIN_OFF);       // [c][row<34][col<36]
        const int job = grp * (GRP_SZ - GRP_MMA) + (rr - GRP_MMA);   // 0..1151
        const int n   = NA + (job >> 6);
        const int t   = job & 63;
        const int x0  = (t & 7) * F_TILE;
        const int y0  = (t >> 3) * F_TILE;

        // weights: identity copy, splatted, +m padding
        for (int i = tid; i < 576; i += 256) {
            unsigned wv = __float_as_uint(flt[i]);
            ws[i + i / 72] = pack2(wv, wv);     // index = m*73 + c*9 + r*3 + s
        }

        // input staging: 2448 float4 (8c x 34row x 9), zero OOB
        const float* inb = in + (size_t)n * (C_IN * HW * HW);
        #pragma unroll 1
        for (int i = tid; i < C_IN * F_IN_H * 9; i += 256) {
            int col4 = i % 9;
            int tt   = i / 9;
            int row  = tt % F_IN_H;
            int c    = tt / F_IN_H;
            int gy = y0 + row, gx = x0 + col4 * 4;
            float4 v = make_float4(0.f, 0.f, 0.f, 0.f);
            if (gy < HW && gx < HW)
                v = *(const float4*)(inb + (c * HW + gy) * HW + gx);
            *(float4*)(sinf + c * F_CSTR + row * F_IN_W + col4 * 4) = v;
        }
        __syncthreads();

        const int lane = tid & 31;
        const int txi  = lane & 7;                       // x = x0 + 4*txi
        const int g    = (lane >> 3) & 1;                // m half
        const int tyi  = ((tid >> 5) << 1) | (lane >> 4); // 0..15: rows 2tyi, +1
        const int mbase = g * 4;

        ULL acc[4][2][2];
        #pragma unroll
        for (int mi = 0; mi < 4; mi++)
            #pragma unroll
            for (int o = 0; o < 2; o++) {
                acc[mi][o][0] = 0ull;
                acc[mi][o][1] = 0ull;
            }

        #pragma unroll 1
        for (int c = 0; c < C_IN; c++) {
            const float* p = sinf + c * F_CSTR + (2 * tyi) * F_IN_W + txi * 4;

            ULL A[4], B[4], D[4], O0[4], O1[4];
            #pragma unroll
            for (int ir = 0; ir < 4; ir++) {
                A[ir] = *(const ULL*)(p + ir * F_IN_W);
                B[ir] = *(const ULL*)(p + ir * F_IN_W + 2);
                D[ir] = *(const ULL*)(p + ir * F_IN_W + 4);
            }
            #pragma unroll
            for (int ir = 0; ir < 4; ir++) {
                unsigned al, ah, bl, bh, dl, dh;
                unpack2(A[ir], al, ah);
                unpack2(B[ir], bl, bh);
                unpack2(D[ir], dl, dh);
                O0[ir] = pack2(ah, bl);
                O1[ir] = pack2(bh, dl);
            }

            #pragma unroll
            for (int mi = 0; mi < 4; mi++) {
                const ULL* wp = ws + (mbase + mi) * 73 + c * 9;
                ULL wr[9];
                #pragma unroll
                for (int k = 0; k < 9; k++) wr[k] = wp[k];

                #pragma unroll
                for (int r = 0; r < 3; r++) {
                    #pragma unroll
                    for (int o = 0; o < 2; o++) {
                        const int ir = r + o;
                        acc[mi][o][0] = fma2(A[ir],  wr[3 * r + 0], acc[mi][o][0]);
                        acc[mi][o][0] = fma2(O0[ir], wr[3 * r + 1], acc[mi][o][0]);
                        acc[mi][o][0] = fma2(B[ir],  wr[3 * r + 2], acc[mi][o][0]);
                        acc[mi][o][1] = fma2(B[ir],  wr[3 * r + 0], acc[mi][o][1]);
                        acc[mi][o][1] = fma2(O1[ir], wr[3 * r + 1], acc[mi][o][1]);
                        acc[mi][o][1] = fma2(D[ir],  wr[3 * r + 2], acc[mi][o][1]);
                    }
                }
            }
        }

        const int x = x0 + txi * 4;   // <= 252
        #pragma unroll
        for (int mi = 0; mi < 4; mi++) {
            float* ob = out + (size_t)(n * M_OUT + mbase + mi) * PLANE;
            #pragma unroll
            for (int o = 0; o < 2; o++) {
                const int y = y0 + 2 * tyi + o;
                if (y < P_OUT) {
                    unsigned lo, hi;
                    unpack2(acc[mi][o][0], lo, hi);
                    *(float2*)(ob + (size_t)y * P_OUT + x) =
                        make_float2(__uint_as_float(lo), __uint_as_float(hi));
                    if (x + 3 < P_OUT) {
                        unpack2(acc[mi][o][1], lo, hi);
                        *(float2*)(ob + (size_t)y * P_OUT + x + 2) =
                            make_float2(__uint_as_float(lo), __uint_as_float(hi));
                    }
                }
            }
        }
    }
}

extern "C" void kernel_launch(void* const* d_in, const int* in_sizes, int n_in,
                              void* d_out, int out_size) {
    const float* in  = (const float*)d_in[0];   // (64, 8, 256, 256) fp32
    const float* flt = (const float*)d_in[1];   // (8, 8, 3, 3) fp32 OIHW
    float* out = (float*)d_out;                 // (64, 8, 254, 254) fp32

    (void)in_sizes; (void)n_in; (void)out_size;

    cudaFuncSetAttribute(conv_hybrid_kernel,
                         cudaFuncAttributeMaxDynamicSharedMemorySize, SMEM_BYTES);

    conv_hybrid_kernel<<<TOTAL_BLKS, 256, SMEM_BYTES>>>(in, flt, out);
}

// round 14
// speedup vs baseline: 2.0064x; 2.0064x over previous
#include <cuda_runtime.h>
#include <cuda_fp16.h>
#include <stdint.h>

// ---------------- problem constants ----------------
#define C_IN   8
#define HW     256
#define M_OUT  8
#define P_OUT  254
#define PLANE  (P_OUT * P_OUT)

// ---------------- tiling ----------------
#define YB         8                          // output rows per block
#define ROWS_ST    (YB + 2)                   // 10 staged input rows
#define CH2_STRIDE 264                        // half2 words per (row,c2); mod32==8 -> conflict-free
#define ROW_STRIDE_H (4 * CH2_STRIDE)         // 1056 words per staged row (4 channel-pairs)
#define SMEM_WORDS (ROWS_ST * ROW_STRIDE_H)   // 10560
#define SMEM_BYTES (SMEM_WORDS * 4)           // 42240

__device__ __forceinline__ uint32_t packh2(float lo, float hi) {
    __half2 h = __floats2half2_rn(lo, hi);    // .x = lo half, .y = hi half
    return *(uint32_t*)&h;
}

// 6 half2 words for one staged row: px g+0..2 and g+8..10 (channel pair tig)
__device__ __forceinline__ void load6(uint32_t* W, const uint32_t* q) {
    W[0] = q[0]; W[1] = q[1]; W[2] = q[2];
    W[3] = q[8]; W[4] = q[9]; W[5] = q[10];
}

#define MMA16(d, a0, a1, a2, a3, b0, b1)                                     \
    asm volatile("mma.sync.aligned.m16n8k16.row.col.f32.f16.f16.f32 "        \
                 "{%0,%1,%2,%3}, {%4,%5,%6,%7}, {%8,%9}, {%0,%1,%2,%3};"     \
                 : "+f"(d[0]), "+f"(d[1]), "+f"(d[2]), "+f"(d[3])            \
                 : "r"(a0), "r"(a1), "r"(a2), "r"(a3), "r"(b0), "r"(b1))

#define MMA8(d, a0, a1, b0)                                                  \
    asm volatile("mma.sync.aligned.m16n8k8.row.col.f32.f16.f16.f32 "         \
                 "{%0,%1,%2,%3}, {%4,%5}, {%6}, {%0,%1,%2,%3};"              \
                 : "+f"(d[0]), "+f"(d[1]), "+f"(d[2]), "+f"(d[3])            \
                 : "r"(a0), "r"(a1), "r"(b0))

__global__ __launch_bounds__(256, 2)
void conv_mma_kernel(const float* __restrict__ in,
                     const float* __restrict__ flt,
                     float* __restrict__ out) {
    extern __shared__ uint32_t sin_[];   // half2: [row 0..9][c2 0..3][px s264]

    const int tid  = threadIdx.x;
    const int w    = tid >> 5;
    const int lane = tid & 31;
    const int gid  = lane >> 2;       // 0..7 pixel group
    const int tig  = lane & 3;        // 0..3 channel-pair group
    const int n    = blockIdx.y;
    const int y0   = blockIdx.x * YB;

    const float* inb = in + (size_t)n * (C_IN * HW * HW);

    // ---- stage rows y0..y0+9: interleave channel pairs as half2 (zero OOB) ----
    #pragma unroll
    for (int it = 0; it < 10; it++) {
        int i   = tid + it * 256;     // 0..2559
        int row = i >> 8;             // 0..9
        int c2  = (i >> 6) & 3;
        int x4  = i & 63;
        int gy  = y0 + row;
        float4 v = make_float4(0.f, 0.f, 0.f, 0.f);
        float4 u = make_float4(0.f, 0.f, 0.f, 0.f);
        if (gy < HW) {
            v = *(const float4*)(inb + ((2 * c2    ) * HW + gy) * HW + x4 * 4);
            u = *(const float4*)(inb + ((2 * c2 + 1) * HW + gy) * HW + x4 * 4);
        }
        uint4 t = make_uint4(packh2(v.x, u.x), packh2(v.y, u.y),
                             packh2(v.z, u.z), packh2(v.w, u.w));
        *(uint4*)(sin_ + row * ROW_STRIDE_H + c2 * CH2_STRIDE + x4 * 4) = t;
    }
    // zero pad words px 256..263 (loads touch up to px 257)
    for (int i = tid; i < ROWS_ST * 4 * 8; i += 256) {
        int row = i >> 5;
        int c2  = (i >> 3) & 3;
        sin_[row * ROW_STRIDE_H + c2 * CH2_STRIDE + 256 + (i & 7)] = 0u;
    }

    // ---- B fragments: wb[rs] = half2(W[m=gid][c=2tig][r][s], W[gid][2tig+1][r][s]) ----
    uint32_t wb[9];
    #pragma unroll
    for (int rs = 0; rs < 9; rs++) {
        int r = rs / 3, s = rs % 3;
        float we = flt[((gid * 8 + 2 * tig    ) * 3 + r) * 3 + s];
        float wo = flt[((gid * 8 + 2 * tig + 1) * 3 + r) * 3 + s];
        wb[rs] = packh2(we, wo);
    }
    __syncthreads();

    // ---- each warp: 2 x-columns of 16 px, sweep 8 y-rows with ring-3 half2 words ----
    #pragma unroll 1
    for (int col = 0; col < 2; col++) {
        const int xb = (w + col * 8) * 16;
        const int g  = xb + gid;            // px group0, <= 247
        const uint32_t* base = sin_ + tig * CH2_STRIDE + g;

        uint32_t W[3][6];
        load6(W[0], base + 0 * ROW_STRIDE_H);
        load6(W[1], base + 1 * ROW_STRIDE_H);

        #pragma unroll
        for (int yi = 0; yi < YB; yi++) {
            load6(W[(yi + 2) % 3], base + (yi + 2) * ROW_STRIDE_H);

            const uint32_t* R0 = W[yi % 3];          // input row y+0
            const uint32_t* R1 = W[(yi + 1) % 3];    // y+1
            const uint32_t* R2 = W[(yi + 2) % 3];    // y+2

            // K packing: k = j*8 + c ; combos per MMA: (j0, j1)
            float aA[4] = {0.f, 0.f, 0.f, 0.f};
            float aB[4] = {0.f, 0.f, 0.f, 0.f};
            // P0 = ((r0,s0),(r0,s1))
            MMA16(aA, R0[0], R0[3], R0[1], R0[4], wb[0], wb[1]);
            // P2 = ((r1,s1),(r1,s2))
            MMA16(aB, R1[1], R1[4], R1[2], R1[5], wb[4], wb[5]);
            // P1 = ((r0,s2),(r1,s0))
            MMA16(aA, R0[2], R0[5], R1[0], R1[3], wb[2], wb[3]);
            // P3 = ((r2,s0),(r2,s1))
            MMA16(aB, R2[0], R2[3], R2[1], R2[4], wb[6], wb[7]);
            // K8 = (r2,s2)
            MMA8(aA, R2[2], R2[5], wb[8]);

            const int y = y0 + yi;
            if (y < P_OUT) {
                float c0 = aA[0] + aB[0];
                float c1 = aA[1] + aB[1];
                float c2v = aA[2] + aB[2];
                float c3 = aA[3] + aB[3];
                // C: c0:(px g, m 2tig) c1:(g, 2tig+1) c2:(g+8, 2tig) c3:(g+8, 2tig+1)
                float* ob = out + (size_t)(n * M_OUT) * PLANE + (size_t)y * P_OUT;
                ob[(2 * tig    ) * PLANE + g] = c0;
                ob[(2 * tig + 1) * PLANE + g] = c1;
                if (g + 8 < P_OUT) {
                    ob[(2 * tig    ) * PLANE + g + 8] = c2v;
                    ob[(2 * tig + 1) * PLANE + g + 8] = c3;
                }
            }
        }
    }
}

extern "C" void kernel_launch(void* const* d_in, const int* in_sizes, int n_in,
                              void* d_out, int out_size) {
    const float* in  = (const float*)d_in[0];   // (64, 8, 256, 256) fp32
    const float* flt = (const float*)d_in[1];   // (8, 8, 3, 3) fp32 OIHW
    float* out = (float*)d_out;                 // (64, 8, 254, 254) fp32

    (void)in_sizes; (void)n_in; (void)out_size;

    cudaFuncSetAttribute(conv_mma_kernel,
                         cudaFuncAttributeMaxDynamicSharedMemorySize, SMEM_BYTES);

    dim3 grid((P_OUT + YB - 1) / YB, 64);   // 32 y-blocks x 64 n
    conv_mma_kernel<<<grid, 256, SMEM_BYTES>>>(in, flt, out);
}